// round 6
// baseline (speedup 1.0000x reference)
#include <cuda_runtime.h>
#include <math.h>
#include <stdint.h>

#define BB 4
#define TT 2048
#define CC 1024
#define HH 16
#define DD 64
#define BT (BB*TT)   // 8192

// ---------------- scratch (device globals; allocation-free) ----------------
__device__ float g_q [(size_t)BB*HH*TT*DD];   // [B,H,T,D], tf32-rounded
__device__ float g_k [(size_t)BB*HH*TT*DD];   // tf32-rounded
__device__ float g_v [(size_t)BB*HH*TT*DD];   // tf32-rounded
__device__ float g_y [(size_t)BT*CC];         // attn out [B,T,H*D], tf32-rounded
__device__ float g_xr[(size_t)BT*CC];         // x rounded to tf32
__device__ float g_wt[(size_t)3*CC*CC];       // W transposed [z*1024+h*64+d][c], tf32
__device__ float g_wpr[(size_t)CC*CC];        // Wproj rounded [n][c]

// ---------------- helpers ----------------
__device__ __forceinline__ float rntf32(float v) {
    uint32_t r;
    asm("cvt.rna.tf32.f32 %0, %1;" : "=r"(r) : "f"(v));
    return __uint_as_float(r);
}
__device__ __forceinline__ uint32_t smem_u32(const void* p) {
    uint32_t a;
    asm("{ .reg .u64 t; cvta.to.shared.u64 t, %1; cvt.u32.u64 %0, t; }" : "=r"(a) : "l"(p));
    return a;
}
__device__ __forceinline__ void cpa16(uint32_t dst, const void* src) {
    asm volatile("cp.async.cg.shared.global [%0], [%1], 16;" :: "r"(dst), "l"(src));
}
__device__ __forceinline__ void cpa_commit() {
    asm volatile("cp.async.commit_group;" ::: "memory");
}
__device__ __forceinline__ void cpa_wait1() {
    asm volatile("cp.async.wait_group 1;" ::: "memory");
}
__device__ __forceinline__ void cpa_wait0() {
    asm volatile("cp.async.wait_group 0;" ::: "memory");
}
__device__ __forceinline__ void mma_tf32(float c[4], const uint32_t a[4],
                                         const uint32_t b[2]) {
    asm volatile(
        "mma.sync.aligned.m16n8k8.row.col.f32.tf32.tf32.f32 "
        "{%0,%1,%2,%3}, {%4,%5,%6,%7}, {%8,%9}, {%0,%1,%2,%3};"
        : "+f"(c[0]), "+f"(c[1]), "+f"(c[2]), "+f"(c[3])
        : "r"(a[0]), "r"(a[1]), "r"(a[2]), "r"(a[3]), "r"(b[0]), "r"(b[1]));
}

// ---------------------------------------------------------------------------
// Prep: tf32-round a flat array.  which==0 -> g_xr, which==1 -> g_wpr
// ---------------------------------------------------------------------------
__global__ __launch_bounds__(256) void round_kernel(const float* __restrict__ src,
                                                    int which, int n4)
{
    int i = blockIdx.x * blockDim.x + threadIdx.x;
    if (i >= n4) return;
    float* dst = which ? g_wpr : g_xr;
    float4 v = *(const float4*)(src + (size_t)i * 4);
    v.x = rntf32(v.x); v.y = rntf32(v.y); v.z = rntf32(v.z); v.w = rntf32(v.w);
    *(float4*)(dst + (size_t)i * 4) = v;
}

// ---------------------------------------------------------------------------
// Prep: transpose W[z][h][c][d] -> g_wt[(z*1024+h*64+d)][c], tf32-rounded.
// ---------------------------------------------------------------------------
__global__ __launch_bounds__(256) void transpose_w(
    const float* __restrict__ Wq, const float* __restrict__ Wk,
    const float* __restrict__ Wv)
{
    __shared__ float tile[32][33];
    const int zh = blockIdx.z;
    const int z = zh >> 4, h = zh & 15;
    const float* W = (z == 0 ? Wq : (z == 1 ? Wk : Wv)) + (size_t)h * CC * DD;
    const int c0 = blockIdx.x * 32, d0 = blockIdx.y * 32;
    const int tx = threadIdx.x, ty = threadIdx.y;

    #pragma unroll
    for (int i = 0; i < 4; i++) {
        int c = c0 + ty + i * 8;
        tile[ty + i * 8][tx] = rntf32(W[(size_t)c * DD + d0 + tx]);
    }
    __syncthreads();
    const size_t base_n = (size_t)zh * 64;
    #pragma unroll
    for (int i = 0; i < 4; i++) {
        int d = d0 + ty + i * 8;
        g_wt[(base_n + d) * CC + c0 + tx] = tile[tx][ty + i * 8];
    }
}

// ---------------------------------------------------------------------------
// mma.sync tf32 GEMM v2: CTA tile 256x128, 8 warps (4m x 2n), warp tile 64x64,
// k-chunk 32, 3-stage cp.async pipeline, one __syncthreads per chunk.
// MODE 0: QKV (A=g_xr, B=g_wt z-slab; scatter epilogue to g_q/k/v, tf32-rounds)
// MODE 1: proj (A=g_y,  B=g_wpr; +bias, writes d_out)
// ---------------------------------------------------------------------------
#define SROW 36
#define A_STAGE (256 * SROW)                   // floats
#define B_STAGE (128 * SROW)
#define STAGE_FLOATS (A_STAGE + B_STAGE)       // 13824
#define GEMM_SMEM (3 * STAGE_FLOATS * 4)       // 165888 bytes

template <int MODE>
__global__ __launch_bounds__(256, 1) void gemm_kernel(
    const float* __restrict__ bias, float* __restrict__ out)
{
    extern __shared__ __align__(16) float sm[];
    const uint32_t sbase = smem_u32(sm);

    const int tid = threadIdx.x;
    const int lane = tid & 31, wid = tid >> 5;
    const int lr = lane >> 2, la = lane & 3;
    const int wm = wid >> 1;          // 0..3
    const int wn = wid & 1;           // 0..1
    const int m0 = blockIdx.x * 256;
    const int n0 = blockIdx.y * 128;

    const float* A  = (MODE == 0) ? g_xr : g_y;
    const float* Bw = (MODE == 0) ? (g_wt + (size_t)blockIdx.z * CC * CC) : g_wpr;

    // chunk c (k0 = c*32) into stage s
    auto load_chunk = [&](int c, int s) {
        const int k0 = c * 32;
        const uint32_t abase = sbase + (uint32_t)s * STAGE_FLOATS * 4;
        const uint32_t bbase = abase + A_STAGE * 4;
        #pragma unroll
        for (int i = 0; i < 8; i++) {             // A: 256 rows x 8 float4
            int idx = tid + i * 256;
            int row = idx >> 3, seg = idx & 7;
            cpa16(abase + (uint32_t)(row * SROW + seg * 4) * 4,
                  A + (size_t)(m0 + row) * CC + k0 + seg * 4);
        }
        #pragma unroll
        for (int i = 0; i < 4; i++) {             // B: 128 rows x 8 float4
            int idx = tid + i * 256;
            int row = idx >> 3, seg = idx & 7;
            cpa16(bbase + (uint32_t)(row * SROW + seg * 4) * 4,
                  Bw + (size_t)(n0 + row) * CC + k0 + seg * 4);
        }
    };

    load_chunk(0, 0); cpa_commit();
    load_chunk(1, 1); cpa_commit();

    float acc[4][8][4] = {};          // [mt][nt][frag]

    const int NC = CC / 32;           // 32 chunks
    for (int c = 0; c < NC; c++) {
        cpa_wait1();                  // chunk c resident (1 newer group may be in flight)
        __syncthreads();              // also: stage (c+2)%3 fully consumed by all warps
        if (c + 2 < NC) load_chunk(c + 2, (c + 2) % 3);
        cpa_commit();                 // empty group at tail keeps wait arithmetic uniform

        const float* Abase = sm + (c % 3) * STAGE_FLOATS;
        const float* Bbase = Abase + A_STAGE;

        #pragma unroll
        for (int ks = 0; ks < 4; ks++) {
            const int k = ks * 8 + la;
            uint32_t a[4][4], b[8][2];
            #pragma unroll
            for (int mt = 0; mt < 4; mt++) {
                const int m = wm * 64 + mt * 16 + lr;
                a[mt][0] = __float_as_uint(Abase[m * SROW + k]);
                a[mt][1] = __float_as_uint(Abase[(m + 8) * SROW + k]);
                a[mt][2] = __float_as_uint(Abase[m * SROW + k + 4]);
                a[mt][3] = __float_as_uint(Abase[(m + 8) * SROW + k + 4]);
            }
            #pragma unroll
            for (int nt = 0; nt < 8; nt++) {
                const int n = wn * 64 + nt * 8 + lr;
                b[nt][0] = __float_as_uint(Bbase[n * SROW + k]);
                b[nt][1] = __float_as_uint(Bbase[n * SROW + k + 4]);
            }
            #pragma unroll
            for (int mt = 0; mt < 4; mt++)
                #pragma unroll
                for (int nt = 0; nt < 8; nt++)
                    mma_tf32(acc[mt][nt], a[mt], b[nt]);
        }
    }

    // ---- epilogue ----
    #pragma unroll
    for (int mt = 0; mt < 4; mt++) {
        const int m = m0 + wm * 64 + mt * 16 + lr;
        #pragma unroll
        for (int nt = 0; nt < 8; nt++) {
            const int n = n0 + wn * 64 + nt * 8 + 2 * la;
            if (MODE == 0) {
                const int z = blockIdx.z;
                float* outb = (z == 0 ? g_q : (z == 1 ? g_k : g_v));
                const int h = n >> 6, d = n & 63;
                #pragma unroll
                for (int half = 0; half < 2; half++) {
                    const int mm = m + half * 8;
                    const int bb = mm >> 11, t = mm & 2047;
                    float2 o2 = make_float2(rntf32(acc[mt][nt][half * 2]),
                                            rntf32(acc[mt][nt][half * 2 + 1]));
                    *(float2*)(outb + (((size_t)(bb * HH + h) * TT + t) * DD + d)) = o2;
                }
            } else {
                const float2 b2 = *(const float2*)(bias + n);
                #pragma unroll
                for (int half = 0; half < 2; half++) {
                    const int mm = m + half * 8;
                    float2 o2 = make_float2(acc[mt][nt][half * 2] + b2.x,
                                            acc[mt][nt][half * 2 + 1] + b2.y);
                    *(float2*)(out + (size_t)mm * CC + n) = o2;
                }
            }
        }
    }
}

// ---------------------------------------------------------------------------
// Tensor-core causal flash attention (tf32 mma.sync, fp32 softmax) — unchanged.
// ---------------------------------------------------------------------------
#define KSS 68
#define VSS 72
#define PSS 68
#define ATTN_SMEM ((128*PSS + 2*64*KSS + 2*64*VSS) * 4)   // 106496 B

__global__ __launch_bounds__(256) void attn_mma()
{
    extern __shared__ __align__(16) float smf[];
    float* Ps = smf;                         // [128][PSS] (also Q staging)
    float* Ks = smf + 128 * PSS;             // [2][64][KSS]
    float* Vs = Ks + 2 * 64 * KSS;           // [2][64][VSS]
    const uint32_t ks_b = smem_u32(Ks);
    const uint32_t vs_b = smem_u32(Vs);

    const int qt = (gridDim.x - 1) - blockIdx.x;   // heavy tiles first
    const int h = blockIdx.y, b = blockIdx.z;
    const int tid = threadIdx.x, lane = tid & 31, w = tid >> 5;
    const int lr = lane >> 2, la = lane & 3;
    const int q0 = qt * 128;
    const size_t bh = (size_t)(b * HH + h);
    const float* qg = g_q + (bh * TT + q0) * DD;
    const float* kg = g_k + bh * TT * DD;
    const float* vg = g_v + bh * TT * DD;

    auto load_tile = [&](int kt, int buf) {
        const float* ksrc = kg + (size_t)kt * 64 * DD;
        const float* vsrc = vg + (size_t)kt * 64 * DD;
        #pragma unroll
        for (int i = 0; i < 4; i++) {
            int idx = tid + i * 256;
            int row = idx >> 4, seg = idx & 15;
            cpa16(ks_b + (uint32_t)((buf * 64 + row) * KSS + seg * 4) * 4,
                  ksrc + (size_t)row * DD + seg * 4);
            cpa16(vs_b + (uint32_t)((buf * 64 + row) * VSS + seg * 4) * 4,
                  vsrc + (size_t)row * DD + seg * 4);
        }
        cpa_commit();
    };

    load_tile(0, 0);

    #pragma unroll
    for (int i = 0; i < 8; i++) {
        int idx = tid + i * 256;
        int row = idx >> 4, seg = idx & 15;
        *(float4*)&Ps[row * PSS + seg * 4] =
            *(const float4*)&qg[(size_t)row * DD + seg * 4];
    }
    __syncthreads();
    uint32_t qa[8][4];
    const int mrow = w * 16 + lr;
    #pragma unroll
    for (int ks = 0; ks < 8; ks++) {
        const int k = ks * 8 + la;
        qa[ks][0] = __float_as_uint(Ps[mrow * PSS + k] * 0.03125f);
        qa[ks][1] = __float_as_uint(Ps[(mrow + 8) * PSS + k] * 0.03125f);
        qa[ks][2] = __float_as_uint(Ps[mrow * PSS + k + 4] * 0.03125f);
        qa[ks][3] = __float_as_uint(Ps[(mrow + 8) * PSS + k + 4] * 0.03125f);
    }

    float m0 = -1e30f, m1 = -1e30f, l0 = 0.f, l1 = 0.f;
    float oacc[8][4] = {};

    const int nk = 2 * qt + 2;
    const int row0 = q0 + w * 16 + lr;
    const int row1 = row0 + 8;

    for (int kt = 0; kt < nk; kt++) {
        cpa_wait0();
        __syncthreads();
        if (kt + 1 < nk) load_tile(kt + 1, (kt + 1) & 1);

        const float* Kb = Ks + (kt & 1) * 64 * KSS;
        const float* Vb = Vs + (kt & 1) * 64 * VSS;

        float sacc[8][4] = {};
        #pragma unroll
        for (int ks = 0; ks < 8; ks++) {
            const int k = ks * 8 + la;
            #pragma unroll
            for (int nf = 0; nf < 8; nf++) {
                uint32_t bfr[2];
                bfr[0] = __float_as_uint(Kb[(nf * 8 + lr) * KSS + k]);
                bfr[1] = __float_as_uint(Kb[(nf * 8 + lr) * KSS + k + 4]);
                mma_tf32(sacc[nf], qa[ks], bfr);
            }
        }

        const int s_base = kt * 64;
        if (s_base + 63 > q0 + w * 16) {
            #pragma unroll
            for (int nf = 0; nf < 8; nf++) {
                const int s = s_base + nf * 8 + 2 * la;
                if (s > row0)     sacc[nf][0] = -1e30f;
                if (s + 1 > row0) sacc[nf][1] = -1e30f;
                if (s > row1)     sacc[nf][2] = -1e30f;
                if (s + 1 > row1) sacc[nf][3] = -1e30f;
            }
        }

        float mx0 = -1e30f, mx1 = -1e30f;
        #pragma unroll
        for (int nf = 0; nf < 8; nf++) {
            mx0 = fmaxf(mx0, fmaxf(sacc[nf][0], sacc[nf][1]));
            mx1 = fmaxf(mx1, fmaxf(sacc[nf][2], sacc[nf][3]));
        }
        mx0 = fmaxf(mx0, __shfl_xor_sync(0xffffffffu, mx0, 1));
        mx0 = fmaxf(mx0, __shfl_xor_sync(0xffffffffu, mx0, 2));
        mx1 = fmaxf(mx1, __shfl_xor_sync(0xffffffffu, mx1, 1));
        mx1 = fmaxf(mx1, __shfl_xor_sync(0xffffffffu, mx1, 2));
        const float mn0 = fmaxf(m0, mx0), mn1 = fmaxf(m1, mx1);
        const float c0 = __expf(m0 - mn0), c1 = __expf(m1 - mn1);
        float s0 = 0.f, s1 = 0.f;
        #pragma unroll
        for (int nf = 0; nf < 8; nf++) {
            float p0 = __expf(sacc[nf][0] - mn0);
            float p1 = __expf(sacc[nf][1] - mn0);
            float p2 = __expf(sacc[nf][2] - mn1);
            float p3 = __expf(sacc[nf][3] - mn1);
            s0 += p0 + p1; s1 += p2 + p3;
            *(float2*)&Ps[(w * 16 + lr) * PSS + nf * 8 + 2 * la] =
                make_float2(rntf32(p0), rntf32(p1));
            *(float2*)&Ps[(w * 16 + lr + 8) * PSS + nf * 8 + 2 * la] =
                make_float2(rntf32(p2), rntf32(p3));
        }
        s0 += __shfl_xor_sync(0xffffffffu, s0, 1);
        s0 += __shfl_xor_sync(0xffffffffu, s0, 2);
        s1 += __shfl_xor_sync(0xffffffffu, s1, 1);
        s1 += __shfl_xor_sync(0xffffffffu, s1, 2);
        l0 = l0 * c0 + s0;  l1 = l1 * c1 + s1;
        m0 = mn0;           m1 = mn1;
        #pragma unroll
        for (int nf = 0; nf < 8; nf++) {
            oacc[nf][0] *= c0; oacc[nf][1] *= c0;
            oacc[nf][2] *= c1; oacc[nf][3] *= c1;
        }
        __syncwarp();

        #pragma unroll
        for (int ks = 0; ks < 8; ks++) {
            uint32_t pa[4];
            pa[0] = __float_as_uint(Ps[(w * 16 + lr) * PSS + ks * 8 + la]);
            pa[1] = __float_as_uint(Ps[(w * 16 + lr + 8) * PSS + ks * 8 + la]);
            pa[2] = __float_as_uint(Ps[(w * 16 + lr) * PSS + ks * 8 + la + 4]);
            pa[3] = __float_as_uint(Ps[(w * 16 + lr + 8) * PSS + ks * 8 + la + 4]);
            #pragma unroll
            for (int nf = 0; nf < 8; nf++) {
                uint32_t bfr[2];
                bfr[0] = __float_as_uint(Vb[(ks * 8 + la) * VSS + nf * 8 + lr]);
                bfr[1] = __float_as_uint(Vb[(ks * 8 + la + 4) * VSS + nf * 8 + lr]);
                mma_tf32(oacc[nf], pa, bfr);
            }
        }
    }

    const float inv0 = 1.0f / l0, inv1 = 1.0f / l1;
    #pragma unroll
    for (int nf = 0; nf < 8; nf++) {
        const int d = h * 64 + nf * 8 + 2 * la;
        *(float2*)&g_y[(size_t)(b * TT + row0) * CC + d] =
            make_float2(rntf32(oacc[nf][0] * inv0), rntf32(oacc[nf][1] * inv0));
        *(float2*)&g_y[(size_t)(b * TT + row1) * CC + d] =
            make_float2(rntf32(oacc[nf][2] * inv1), rntf32(oacc[nf][3] * inv1));
    }
}

// ---------------------------------------------------------------------------
extern "C" void kernel_launch(void* const* d_in, const int* in_sizes, int n_in,
                              void* d_out, int out_size)
{
    (void)in_sizes; (void)n_in; (void)out_size;
    const float* x  = (const float*)d_in[0];
    const float* Wq = (const float*)d_in[1];
    const float* Wk = (const float*)d_in[2];
    const float* Wv = (const float*)d_in[3];
    const float* Wp = (const float*)d_in[4];
    const float* bp = (const float*)d_in[5];
    float* out = (float*)d_out;

    cudaFuncSetAttribute(attn_mma,
                         cudaFuncAttributeMaxDynamicSharedMemorySize, ATTN_SMEM);
    cudaFuncSetAttribute(gemm_kernel<0>,
                         cudaFuncAttributeMaxDynamicSharedMemorySize, GEMM_SMEM);
    cudaFuncSetAttribute(gemm_kernel<1>,
                         cudaFuncAttributeMaxDynamicSharedMemorySize, GEMM_SMEM);

    round_kernel<<<(BT * CC / 4 + 255) / 256, 256>>>(x, 0, BT * CC / 4);
    round_kernel<<<(CC * CC / 4 + 255) / 256, 256>>>(Wp, 1, CC * CC / 4);
    transpose_w<<<dim3(32, 2, 48), dim3(32, 8)>>>(Wq, Wk, Wv);

    gemm_kernel<0><<<dim3(BT / 256, CC / 128, 3), 256, GEMM_SMEM>>>(nullptr, nullptr);

    attn_mma<<<dim3(TT / 128, HH, BB), 256, ATTN_SMEM>>>();

    gemm_kernel<1><<<dim3(BT / 256, CC / 128, 1), 256, GEMM_SMEM>>>(bp, out);
}

// round 8
// speedup vs baseline: 1.6874x; 1.6874x over previous
#include <cuda_runtime.h>
#include <cuda_fp16.h>
#include <math.h>
#include <stdint.h>

#define BB 4
#define TT 2048
#define CC 1024
#define HH 16
#define DD 64
#define BT (BB*TT)   // 8192

// ---------------- scratch (device globals; allocation-free) ----------------
__device__ __half g_qh [(size_t)BB*HH*TT*DD];   // [B,H,T,D]
__device__ __half g_kh [(size_t)BB*HH*TT*DD];   // [B,H,T,D]
__device__ __half g_vh [(size_t)BB*HH*TT*DD];   // [B,H,D,T]  (transposed!)
__device__ __half g_yh [(size_t)BT*CC];         // attn out [B,T,H*D]
__device__ __half g_xh [(size_t)BT*CC];         // x in fp16
__device__ __half g_wth[(size_t)3*CC*CC];       // W transposed [z*1024+h*64+d][c]
__device__ __half g_wph[(size_t)CC*CC];         // Wproj [n][c]

// ---------------- helpers ----------------
__device__ __forceinline__ uint32_t smem_u32(const void* p) {
    uint32_t a;
    asm("{ .reg .u64 t; cvta.to.shared.u64 t, %1; cvt.u32.u64 %0, t; }" : "=r"(a) : "l"(p));
    return a;
}
__device__ __forceinline__ void cpa16(uint32_t dst, const void* src) {
    asm volatile("cp.async.cg.shared.global [%0], [%1], 16;" :: "r"(dst), "l"(src));
}
__device__ __forceinline__ void cpa_commit() {
    asm volatile("cp.async.commit_group;" ::: "memory");
}
__device__ __forceinline__ void cpa_wait1() {
    asm volatile("cp.async.wait_group 1;" ::: "memory");
}
__device__ __forceinline__ void cpa_wait0() {
    asm volatile("cp.async.wait_group 0;" ::: "memory");
}
// fp16 MMA: D(16x8,f32) += A(16x16,f16) * B(16x8,f16) (row.col)
__device__ __forceinline__ void mma_f16(float c[4], const uint32_t a[4],
                                        const uint32_t b[2]) {
    asm volatile(
        "mma.sync.aligned.m16n8k16.row.col.f32.f16.f16.f32 "
        "{%0,%1,%2,%3}, {%4,%5,%6,%7}, {%8,%9}, {%0,%1,%2,%3};"
        : "+f"(c[0]), "+f"(c[1]), "+f"(c[2]), "+f"(c[3])
        : "r"(a[0]), "r"(a[1]), "r"(a[2]), "r"(a[3]), "r"(b[0]), "r"(b[1]));
}
__device__ __forceinline__ uint32_t pack_h2(float x, float y) {
    __half2 h = __floats2half2_rn(x, y);
    return *(uint32_t*)&h;
}

// ---------------------------------------------------------------------------
// Prep: fp16-convert a flat array. which==0 -> g_xh, which==1 -> g_wph
// ---------------------------------------------------------------------------
__global__ __launch_bounds__(256) void cvt_kernel(const float* __restrict__ src,
                                                  int which, int n4)
{
    int i = blockIdx.x * blockDim.x + threadIdx.x;
    if (i >= n4) return;
    __half* dst = which ? g_wph : g_xh;
    float4 v = *(const float4*)(src + (size_t)i * 4);
    uint2 u;
    u.x = pack_h2(v.x, v.y);
    u.y = pack_h2(v.z, v.w);
    *(uint2*)(dst + (size_t)i * 4) = u;
}

// ---------------------------------------------------------------------------
// Prep: transpose W[z][h][c][d] -> g_wth[(z*1024+h*64+d)][c], fp16.
// ---------------------------------------------------------------------------
__global__ __launch_bounds__(256) void transpose_w(
    const float* __restrict__ Wq, const float* __restrict__ Wk,
    const float* __restrict__ Wv)
{
    __shared__ float tile[32][33];
    const int zh = blockIdx.z;
    const int z = zh >> 4, h = zh & 15;
    const float* W = (z == 0 ? Wq : (z == 1 ? Wk : Wv)) + (size_t)h * CC * DD;
    const int c0 = blockIdx.x * 32, d0 = blockIdx.y * 32;
    const int tx = threadIdx.x, ty = threadIdx.y;

    #pragma unroll
    for (int i = 0; i < 4; i++) {
        int c = c0 + ty + i * 8;
        tile[ty + i * 8][tx] = W[(size_t)c * DD + d0 + tx];
    }
    __syncthreads();
    const size_t base_n = (size_t)zh * 64;
    #pragma unroll
    for (int i = 0; i < 4; i++) {
        int d = d0 + ty + i * 8;
        g_wth[(base_n + d) * CC + c0 + tx] = __float2half_rn(tile[tx][ty + i * 8]);
    }
}

// ---------------------------------------------------------------------------
// fp16 mma.sync GEMM: CTA 256x128, 8 warps (4m x 2n), warp 64x64, k-chunk 32,
// 3-stage cp.async.  MODE 0: QKV (scatter to g_qh/g_kh, g_vh transposed).
// MODE 1: proj (A=g_yh, B=g_wph; +bias -> fp32 d_out).
// Smem rows: 40 halves (32 data + 8 pad) = 20 words; conflict-free fragments.
// ---------------------------------------------------------------------------
#define SROWH 40
#define A_STAGE_B (256 * SROWH * 2)            // 20480 bytes
#define B_STAGE_B (128 * SROWH * 2)            // 10240 bytes
#define STAGE_B   (A_STAGE_B + B_STAGE_B)      // 30720
#define GEMM_SMEM (3 * STAGE_B)                // 92160

template <int MODE>
__global__ __launch_bounds__(256, 1) void gemm_kernel(
    const float* __restrict__ bias, float* __restrict__ out)
{
    extern __shared__ __align__(16) char smc[];
    const uint32_t sbase = smem_u32(smc);

    const int tid = threadIdx.x;
    const int lane = tid & 31, wid = tid >> 5;
    const int lr = lane >> 2, la = lane & 3;
    const int wm = wid >> 1;          // 0..3
    const int wn = wid & 1;           // 0..1
    const int m0 = blockIdx.x * 256;
    const int n0 = blockIdx.y * 128;

    const __half* A  = (MODE == 0) ? g_xh : g_yh;
    const __half* Bw = (MODE == 0) ? (g_wth + (size_t)blockIdx.z * CC * CC) : g_wph;

    // chunk c (k0 = c*32 halves = 4 x 16B segs per row) into stage s
    auto load_chunk = [&](int c, int s) {
        const int k0 = c * 32;
        const uint32_t abase = sbase + (uint32_t)s * STAGE_B;
        const uint32_t bbase = abase + A_STAGE_B;
        #pragma unroll
        for (int i = 0; i < 4; i++) {             // A: 256 rows x 4 segs
            int idx = tid + i * 256;
            int row = idx >> 2, seg = idx & 3;
            cpa16(abase + (uint32_t)(row * SROWH + seg * 8) * 2,
                  A + (size_t)(m0 + row) * CC + k0 + seg * 8);
        }
        #pragma unroll
        for (int i = 0; i < 2; i++) {             // B: 128 rows x 4 segs
            int idx = tid + i * 256;
            int row = idx >> 2, seg = idx & 3;
            cpa16(bbase + (uint32_t)(row * SROWH + seg * 8) * 2,
                  Bw + (size_t)(n0 + row) * CC + k0 + seg * 8);
        }
    };

    load_chunk(0, 0); cpa_commit();
    load_chunk(1, 1); cpa_commit();

    float acc[4][8][4] = {};          // [mt][nt][frag]

    const int NC = CC / 32;           // 32 chunks
    for (int c = 0; c < NC; c++) {
        cpa_wait1();
        __syncthreads();
        if (c + 2 < NC) load_chunk(c + 2, (c + 2) % 3);
        cpa_commit();

        const uint32_t* Aw = (const uint32_t*)(smc + (c % 3) * STAGE_B);
        const uint32_t* Bwd = (const uint32_t*)(smc + (c % 3) * STAGE_B + A_STAGE_B);

        #pragma unroll
        for (int ks = 0; ks < 2; ks++) {          // two k16 steps per chunk
            const int kw = ks * 8 + la;           // word offset within row
            uint32_t a[4][4], b[8][2];
            #pragma unroll
            for (int mt = 0; mt < 4; mt++) {
                const int m = wm * 64 + mt * 16 + lr;
                a[mt][0] = Aw[m * 20 + kw];
                a[mt][1] = Aw[(m + 8) * 20 + kw];
                a[mt][2] = Aw[m * 20 + kw + 4];
                a[mt][3] = Aw[(m + 8) * 20 + kw + 4];
            }
            #pragma unroll
            for (int nt = 0; nt < 8; nt++) {
                const int n = wn * 64 + nt * 8 + lr;
                b[nt][0] = Bwd[n * 20 + kw];
                b[nt][1] = Bwd[n * 20 + kw + 4];
            }
            #pragma unroll
            for (int mt = 0; mt < 4; mt++)
                #pragma unroll
                for (int nt = 0; nt < 8; nt++)
                    mma_f16(acc[mt][nt], a[mt], b[nt]);
        }
    }

    // ---- epilogue ----
    #pragma unroll
    for (int mt = 0; mt < 4; mt++) {
        const int m = m0 + wm * 64 + mt * 16 + lr;
        #pragma unroll
        for (int nt = 0; nt < 8; nt++) {
            const int n = n0 + wn * 64 + nt * 8 + 2 * la;
            if (MODE == 0) {
                const int z = blockIdx.z;
                const int h = n >> 6, d = n & 63;
                #pragma unroll
                for (int half = 0; half < 2; half++) {
                    const int mm = m + half * 8;
                    const int bb = mm >> 11, t = mm & 2047;
                    const size_t bh = (size_t)(bb * HH + h);
                    float v0 = acc[mt][nt][half * 2], v1 = acc[mt][nt][half * 2 + 1];
                    if (z == 2) {
                        // V transposed: [B,H,D,T]
                        g_vh[(bh * DD + d)     * TT + t] = __float2half_rn(v0);
                        g_vh[(bh * DD + d + 1) * TT + t] = __float2half_rn(v1);
                    } else {
                        __half* outb = (z == 0 ? g_qh : g_kh);
                        uint32_t u = pack_h2(v0, v1);
                        *(uint32_t*)(outb + (bh * TT + t) * DD + d) = u;
                    }
                }
            } else {
                const float2 b2 = *(const float2*)(bias + n);
                #pragma unroll
                for (int half = 0; half < 2; half++) {
                    const int mm = m + half * 8;
                    float2 o2 = make_float2(acc[mt][nt][half * 2] + b2.x,
                                            acc[mt][nt][half * 2 + 1] + b2.y);
                    *(float2*)(out + (size_t)mm * CC + n) = o2;
                }
            }
        }
    }
}

// ---------------------------------------------------------------------------
// fp16 tensor-core causal flash attention (fp32 softmax/accum).
// Block 256 / 8 warps; q-tile 128 (warp w: rows w*16..+15); k-tile 64.
// Q frags in regs; K + V^T double-buffered cp.async; P via smem (fp16 pairs).
// Shared strides: 72 halves = 36 words, conflict-free for all patterns.
// ---------------------------------------------------------------------------
#define AQSS 72                                  // halves
#define ATTN_SMEM ((128 + 2*64 + 2*64) * AQSS * 2)   // 55296 B

__global__ __launch_bounds__(256) void attn_mma()
{
    extern __shared__ __align__(16) char smc[];
    __half* PQ = (__half*)smc;                      // [128][72] (Q staging + P)
    __half* Ks = PQ + 128 * AQSS;                   // [2][64][72]
    __half* Vt = Ks + 2 * 64 * AQSS;                // [2][64][72]  rows = d!
    uint32_t* PQw = (uint32_t*)PQ;
    const uint32_t ks_b = smem_u32(Ks);
    const uint32_t vt_b = smem_u32(Vt);

    const int qt = (gridDim.x - 1) - blockIdx.x;    // heavy tiles first
    const int h = blockIdx.y, b = blockIdx.z;
    const int tid = threadIdx.x, lane = tid & 31, w = tid >> 5;
    const int lr = lane >> 2, la = lane & 3;
    const int q0 = qt * 128;
    const size_t bh = (size_t)(b * HH + h);
    const __half* qg = g_qh + (bh * TT + q0) * DD;
    const __half* kg = g_kh + bh * TT * DD;
    const __half* vg = g_vh + bh * DD * TT;         // [d][t]

    // 64x64-half tile = 64 rows x 8 x 16B segments = 512 cpa16 (2 x 256 thr)
    auto load_tile = [&](int kt, int buf) {
        const __half* ksrc = kg + (size_t)kt * 64 * DD;
        #pragma unroll
        for (int i = 0; i < 2; i++) {               // K
            int idx = tid + i * 256;
            int row = idx >> 3, seg = idx & 7;
            cpa16(ks_b + (uint32_t)((buf * 64 + row) * AQSS + seg * 8) * 2,
                  ksrc + (size_t)row * DD + seg * 8);
        }
        #pragma unroll
        for (int i = 0; i < 2; i++) {               // V^T (rows = d)
            int idx = tid + i * 256;
            int row = idx >> 3, seg = idx & 7;
            cpa16(vt_b + (uint32_t)((buf * 64 + row) * AQSS + seg * 8) * 2,
                  vg + (size_t)row * TT + kt * 64 + seg * 8);
        }
        cpa_commit();
    };

    load_tile(0, 0);

    // stage Q (coalesced)
    #pragma unroll
    for (int i = 0; i < 4; i++) {
        int idx = tid + i * 256;
        int row = idx >> 3, seg = idx & 7;
        *(uint4*)&PQ[row * AQSS + seg * 8] =
            *(const uint4*)&qg[(size_t)row * DD + seg * 8];
    }
    __syncthreads();

    // pull Q fragments, scaled by C^-0.5 = 2^-5 (exact in fp16)
    uint32_t qa[4][4];
    const int mrow = w * 16 + lr;
    #pragma unroll
    for (int ks = 0; ks < 4; ks++) {
        const int kw = ks * 8 + la;
        #pragma unroll
        for (int j = 0; j < 4; j++) {
            const int rr = (j & 1) ? mrow + 8 : mrow;
            const int cc = kw + ((j >> 1) ? 4 : 0);
            uint32_t u = PQw[rr * 36 + cc];
            float2 f = __half22float2(*(__half2*)&u);
            qa[ks][j] = pack_h2(f.x * 0.03125f, f.y * 0.03125f);
        }
    }

    float m0 = -1e30f, m1 = -1e30f, l0 = 0.f, l1 = 0.f;
    float oacc[8][4] = {};

    const int nk = 2 * qt + 2;
    const int row0 = q0 + w * 16 + lr;
    const int row1 = row0 + 8;

    for (int kt = 0; kt < nk; kt++) {
        cpa_wait0();
        __syncthreads();
        if (kt + 1 < nk) load_tile(kt + 1, (kt + 1) & 1);

        const uint32_t* Kb = (const uint32_t*)(Ks + (kt & 1) * 64 * AQSS);
        const uint32_t* Vb = (const uint32_t*)(Vt + (kt & 1) * 64 * AQSS);

        // ---- S = Q K^T ----
        float sacc[8][4] = {};
        #pragma unroll
        for (int ks = 0; ks < 4; ks++) {
            const int kw = ks * 8 + la;
            #pragma unroll
            for (int nf = 0; nf < 8; nf++) {
                uint32_t bfr[2];
                bfr[0] = Kb[(nf * 8 + lr) * 36 + kw];
                bfr[1] = Kb[(nf * 8 + lr) * 36 + kw + 4];
                mma_f16(sacc[nf], qa[ks], bfr);
            }
        }

        // ---- causal mask ----
        const int s_base = kt * 64;
        if (s_base + 63 > q0 + w * 16) {
            #pragma unroll
            for (int nf = 0; nf < 8; nf++) {
                const int s = s_base + nf * 8 + 2 * la;
                if (s > row0)     sacc[nf][0] = -1e30f;
                if (s + 1 > row0) sacc[nf][1] = -1e30f;
                if (s > row1)     sacc[nf][2] = -1e30f;
                if (s + 1 > row1) sacc[nf][3] = -1e30f;
            }
        }

        // ---- online softmax ----
        float mx0 = -1e30f, mx1 = -1e30f;
        #pragma unroll
        for (int nf = 0; nf < 8; nf++) {
            mx0 = fmaxf(mx0, fmaxf(sacc[nf][0], sacc[nf][1]));
            mx1 = fmaxf(mx1, fmaxf(sacc[nf][2], sacc[nf][3]));
        }
        mx0 = fmaxf(mx0, __shfl_xor_sync(0xffffffffu, mx0, 1));
        mx0 = fmaxf(mx0, __shfl_xor_sync(0xffffffffu, mx0, 2));
        mx1 = fmaxf(mx1, __shfl_xor_sync(0xffffffffu, mx1, 1));
        mx1 = fmaxf(mx1, __shfl_xor_sync(0xffffffffu, mx1, 2));
        const float mn0 = fmaxf(m0, mx0), mn1 = fmaxf(m1, mx1);
        const float c0 = __expf(m0 - mn0), c1 = __expf(m1 - mn1);
        float s0 = 0.f, s1 = 0.f;
        #pragma unroll
        for (int nf = 0; nf < 8; nf++) {
            float p0 = __expf(sacc[nf][0] - mn0);
            float p1 = __expf(sacc[nf][1] - mn0);
            float p2 = __expf(sacc[nf][2] - mn1);
            float p3 = __expf(sacc[nf][3] - mn1);
            s0 += p0 + p1; s1 += p2 + p3;
            PQw[(w * 16 + lr)     * 36 + nf * 4 + la] = pack_h2(p0, p1);
            PQw[(w * 16 + lr + 8) * 36 + nf * 4 + la] = pack_h2(p2, p3);
        }
        s0 += __shfl_xor_sync(0xffffffffu, s0, 1);
        s0 += __shfl_xor_sync(0xffffffffu, s0, 2);
        s1 += __shfl_xor_sync(0xffffffffu, s1, 1);
        s1 += __shfl_xor_sync(0xffffffffu, s1, 2);
        l0 = l0 * c0 + s0;  l1 = l1 * c1 + s1;
        m0 = mn0;           m1 = mn1;
        #pragma unroll
        for (int nf = 0; nf < 8; nf++) {
            oacc[nf][0] *= c0; oacc[nf][1] *= c0;
            oacc[nf][2] *= c1; oacc[nf][3] *= c1;
        }
        __syncwarp();    // P visible within warp

        // ---- O += P V  (B operand from V^T: k-pairs along s, contiguous) ----
        #pragma unroll
        for (int ks = 0; ks < 4; ks++) {
            const int kw = ks * 8 + la;
            uint32_t pa[4];
            pa[0] = PQw[(w * 16 + lr)     * 36 + kw];
            pa[1] = PQw[(w * 16 + lr + 8) * 36 + kw];
            pa[2] = PQw[(w * 16 + lr)     * 36 + kw + 4];
            pa[3] = PQw[(w * 16 + lr + 8) * 36 + kw + 4];
            #pragma unroll
            for (int nf = 0; nf < 8; nf++) {
                uint32_t bfr[2];
                bfr[0] = Vb[(nf * 8 + lr) * 36 + kw];
                bfr[1] = Vb[(nf * 8 + lr) * 36 + kw + 4];
                mma_f16(oacc[nf], pa, bfr);
            }
        }
    }

    // ---- normalize, write concat layout fp16 ----
    const float inv0 = 1.0f / l0, inv1 = 1.0f / l1;
    #pragma unroll
    for (int nf = 0; nf < 8; nf++) {
        const int d = h * 64 + nf * 8 + 2 * la;
        *(uint32_t*)&g_yh[(size_t)(b * TT + row0) * CC + d] =
            pack_h2(oacc[nf][0] * inv0, oacc[nf][1] * inv0);
        *(uint32_t*)&g_yh[(size_t)(b * TT + row1) * CC + d] =
            pack_h2(oacc[nf][2] * inv1, oacc[nf][3] * inv1);
    }
}

// ---------------------------------------------------------------------------
extern "C" void kernel_launch(void* const* d_in, const int* in_sizes, int n_in,
                              void* d_out, int out_size)
{
    (void)in_sizes; (void)n_in; (void)out_size;
    const float* x  = (const float*)d_in[0];
    const float* Wq = (const float*)d_in[1];
    const float* Wk = (const float*)d_in[2];
    const float* Wv = (const float*)d_in[3];
    const float* Wp = (const float*)d_in[4];
    const float* bp = (const float*)d_in[5];
    float* out = (float*)d_out;

    cudaFuncSetAttribute(attn_mma,
                         cudaFuncAttributeMaxDynamicSharedMemorySize, ATTN_SMEM);
    cudaFuncSetAttribute(gemm_kernel<0>,
                         cudaFuncAttributeMaxDynamicSharedMemorySize, GEMM_SMEM);
    cudaFuncSetAttribute(gemm_kernel<1>,
                         cudaFuncAttributeMaxDynamicSharedMemorySize, GEMM_SMEM);

    cvt_kernel<<<(BT * CC / 4 + 255) / 256, 256>>>(x, 0, BT * CC / 4);
    cvt_kernel<<<(CC * CC / 4 + 255) / 256, 256>>>(Wp, 1, CC * CC / 4);
    transpose_w<<<dim3(32, 2, 48), dim3(32, 8)>>>(Wq, Wk, Wv);

    gemm_kernel<0><<<dim3(BT / 256, CC / 128, 3), 256, GEMM_SMEM>>>(nullptr, nullptr);

    attn_mma<<<dim3(TT / 128, HH, BB), 256, ATTN_SMEM>>>();

    gemm_kernel<1><<<dim3(BT / 256, CC / 128, 1), 256, GEMM_SMEM>>>(bp, out);
}

// round 9
// speedup vs baseline: 1.7958x; 1.0643x over previous
#include <cuda_runtime.h>
#include <cuda_fp16.h>
#include <math.h>
#include <stdint.h>

#define BB 4
#define TT 2048
#define CC 1024
#define HH 16
#define DD 64
#define BT (BB*TT)   // 8192

// ---------------- scratch (device globals; allocation-free) ----------------
__device__ __half g_qh [(size_t)BB*HH*TT*DD];   // [B,H,T,D]
__device__ __half g_kh [(size_t)BB*HH*TT*DD];   // [B,H,T,D]
__device__ __half g_vh [(size_t)BB*HH*TT*DD];   // [B,H,D,T]  (transposed!)
__device__ __half g_yh [(size_t)BT*CC];         // attn out [B,T,H*D]
__device__ __half g_xh [(size_t)BT*CC];         // x in fp16
__device__ __half g_wth[(size_t)3*CC*CC];       // W transposed [z*1024+h*64+d][c]
__device__ __half g_wph[(size_t)CC*CC];         // Wproj [n][c]

// ---------------- helpers ----------------
__device__ __forceinline__ uint32_t smem_u32(const void* p) {
    uint32_t a;
    asm("{ .reg .u64 t; cvta.to.shared.u64 t, %1; cvt.u32.u64 %0, t; }" : "=r"(a) : "l"(p));
    return a;
}
__device__ __forceinline__ void cpa16(uint32_t dst, const void* src) {
    asm volatile("cp.async.cg.shared.global [%0], [%1], 16;" :: "r"(dst), "l"(src));
}
__device__ __forceinline__ void cpa_commit() {
    asm volatile("cp.async.commit_group;" ::: "memory");
}
__device__ __forceinline__ void cpa_wait1() {
    asm volatile("cp.async.wait_group 1;" ::: "memory");
}
__device__ __forceinline__ void cpa_wait0() {
    asm volatile("cp.async.wait_group 0;" ::: "memory");
}
__device__ __forceinline__ void mma_f16(float c[4], const uint32_t a[4],
                                        const uint32_t b[2]) {
    asm volatile(
        "mma.sync.aligned.m16n8k16.row.col.f32.f16.f16.f32 "
        "{%0,%1,%2,%3}, {%4,%5,%6,%7}, {%8,%9}, {%0,%1,%2,%3};"
        : "+f"(c[0]), "+f"(c[1]), "+f"(c[2]), "+f"(c[3])
        : "r"(a[0]), "r"(a[1]), "r"(a[2]), "r"(a[3]), "r"(b[0]), "r"(b[1]));
}
__device__ __forceinline__ void ldsm4(uint32_t r[4], uint32_t addr) {
    asm volatile("ldmatrix.sync.aligned.m8n8.x4.shared.b16 {%0,%1,%2,%3}, [%4];"
        : "=r"(r[0]), "=r"(r[1]), "=r"(r[2]), "=r"(r[3]) : "r"(addr));
}
__device__ __forceinline__ uint32_t pack_h2(float x, float y) {
    __half2 h = __floats2half2_rn(x, y);
    return *(uint32_t*)&h;
}

// ---------------------------------------------------------------------------
// Prep: fp16-convert a flat array. which==0 -> g_xh, which==1 -> g_wph
// ---------------------------------------------------------------------------
__global__ __launch_bounds__(256) void cvt_kernel(const float* __restrict__ src,
                                                  int which, int n4)
{
    int i = blockIdx.x * blockDim.x + threadIdx.x;
    if (i >= n4) return;
    __half* dst = which ? g_wph : g_xh;
    float4 v = *(const float4*)(src + (size_t)i * 4);
    uint2 u;
    u.x = pack_h2(v.x, v.y);
    u.y = pack_h2(v.z, v.w);
    *(uint2*)(dst + (size_t)i * 4) = u;
}

// ---------------------------------------------------------------------------
// Prep: transpose W[z][h][c][d] -> g_wth[(z*1024+h*64+d)][c], fp16.
// ---------------------------------------------------------------------------
__global__ __launch_bounds__(256) void transpose_w(
    const float* __restrict__ Wq, const float* __restrict__ Wk,
    const float* __restrict__ Wv)
{
    __shared__ float tile[32][33];
    const int zh = blockIdx.z;
    const int z = zh >> 4, h = zh & 15;
    const float* W = (z == 0 ? Wq : (z == 1 ? Wk : Wv)) + (size_t)h * CC * DD;
    const int c0 = blockIdx.x * 32, d0 = blockIdx.y * 32;
    const int tx = threadIdx.x, ty = threadIdx.y;

    #pragma unroll
    for (int i = 0; i < 4; i++) {
        int c = c0 + ty + i * 8;
        tile[ty + i * 8][tx] = W[(size_t)c * DD + d0 + tx];
    }
    __syncthreads();
    const size_t base_n = (size_t)zh * 64;
    #pragma unroll
    for (int i = 0; i < 4; i++) {
        int d = d0 + ty + i * 8;
        g_wth[(base_n + d) * CC + c0 + tx] = __float2half_rn(tile[tx][ty + i * 8]);
    }
}

// ---------------------------------------------------------------------------
// fp16 mma.sync GEMM: CTA 256x128, 8 warps (4m x 2n), warp 64x64, k-chunk 32,
// 3-stage cp.async, ldmatrix fragment loads.
// MODE 0: QKV (scatter to g_qh/g_kh, g_vh transposed). MODE 1: proj (+bias).
// ---------------------------------------------------------------------------
#define SROWH 40
#define A_STAGE_B (256 * SROWH * 2)            // 20480 bytes
#define B_STAGE_B (128 * SROWH * 2)            // 10240 bytes
#define STAGE_B   (A_STAGE_B + B_STAGE_B)      // 30720
#define GEMM_SMEM (3 * STAGE_B)                // 92160

template <int MODE>
__global__ __launch_bounds__(256, 1) void gemm_kernel(
    const float* __restrict__ bias, float* __restrict__ out)
{
    extern __shared__ __align__(16) char smc[];
    const uint32_t sbase = smem_u32(smc);

    const int tid = threadIdx.x;
    const int lane = tid & 31, wid = tid >> 5;
    const int lr = lane >> 2, la = lane & 3;
    const int wm = wid >> 1;          // 0..3
    const int wn = wid & 1;           // 0..1
    const int m0 = blockIdx.x * 256;
    const int n0 = blockIdx.y * 128;

    // ldmatrix per-lane row/col offsets (halves)
    const int arow = (lane & 7) + ((lane & 8)  ? 8 : 0);  // A/P: lanes 8-15 -> +8 rows
    const int acol = (lane & 16) ? 8 : 0;                 //      lanes 16+ -> +8 k
    const int brow = (lane & 7) + ((lane & 16) ? 8 : 0);  // B: lanes 16+ -> +8 rows
    const int bcol = (lane & 8) ? 8 : 0;                  //    lanes 8-15 -> +8 k

    const __half* A  = (MODE == 0) ? g_xh : g_yh;
    const __half* Bw = (MODE == 0) ? (g_wth + (size_t)blockIdx.z * CC * CC) : g_wph;

    auto load_chunk = [&](int c, int s) {
        const int k0 = c * 32;
        const uint32_t abase = sbase + (uint32_t)s * STAGE_B;
        const uint32_t bbase = abase + A_STAGE_B;
        #pragma unroll
        for (int i = 0; i < 4; i++) {             // A: 256 rows x 4 segs
            int idx = tid + i * 256;
            int row = idx >> 2, seg = idx & 3;
            cpa16(abase + (uint32_t)(row * SROWH + seg * 8) * 2,
                  A + (size_t)(m0 + row) * CC + k0 + seg * 8);
        }
        #pragma unroll
        for (int i = 0; i < 2; i++) {             // B: 128 rows x 4 segs
            int idx = tid + i * 256;
            int row = idx >> 2, seg = idx & 3;
            cpa16(bbase + (uint32_t)(row * SROWH + seg * 8) * 2,
                  Bw + (size_t)(n0 + row) * CC + k0 + seg * 8);
        }
    };

    load_chunk(0, 0); cpa_commit();
    load_chunk(1, 1); cpa_commit();

    float acc[4][8][4] = {};          // [mt][nt][frag]

    const int NC = CC / 32;           // 32 chunks
    for (int c = 0; c < NC; c++) {
        cpa_wait1();
        __syncthreads();
        if (c + 2 < NC) load_chunk(c + 2, (c + 2) % 3);
        cpa_commit();

        const uint32_t aab = sbase + (uint32_t)(c % 3) * STAGE_B;
        const uint32_t bab = aab + A_STAGE_B;

        #pragma unroll
        for (int ks = 0; ks < 2; ks++) {          // two k16 steps per chunk
            uint32_t a[4][4], b[8][2];
            #pragma unroll
            for (int mt = 0; mt < 4; mt++)
                ldsm4(a[mt], aab + (uint32_t)((wm * 64 + mt * 16 + arow) * SROWH
                                              + ks * 16 + acol) * 2);
            #pragma unroll
            for (int nt2 = 0; nt2 < 4; nt2++) {
                uint32_t r[4];
                ldsm4(r, bab + (uint32_t)((wn * 64 + nt2 * 16 + brow) * SROWH
                                          + ks * 16 + bcol) * 2);
                b[2 * nt2][0] = r[0];     b[2 * nt2][1] = r[1];
                b[2 * nt2 + 1][0] = r[2]; b[2 * nt2 + 1][1] = r[3];
            }
            #pragma unroll
            for (int mt = 0; mt < 4; mt++)
                #pragma unroll
                for (int nt = 0; nt < 8; nt++)
                    mma_f16(acc[mt][nt], a[mt], b[nt]);
        }
    }

    // ---- epilogue ----
    #pragma unroll
    for (int mt = 0; mt < 4; mt++) {
        const int m = m0 + wm * 64 + mt * 16 + lr;
        #pragma unroll
        for (int nt = 0; nt < 8; nt++) {
            const int n = n0 + wn * 64 + nt * 8 + 2 * la;
            if (MODE == 0) {
                const int z = blockIdx.z;
                const int h = n >> 6, d = n & 63;
                #pragma unroll
                for (int half = 0; half < 2; half++) {
                    const int mm = m + half * 8;
                    const int bb = mm >> 11, t = mm & 2047;
                    const size_t bh = (size_t)(bb * HH + h);
                    float v0 = acc[mt][nt][half * 2], v1 = acc[mt][nt][half * 2 + 1];
                    if (z == 2) {
                        g_vh[(bh * DD + d)     * TT + t] = __float2half_rn(v0);
                        g_vh[(bh * DD + d + 1) * TT + t] = __float2half_rn(v1);
                    } else {
                        __half* outb = (z == 0 ? g_qh : g_kh);
                        uint32_t u = pack_h2(v0, v1);
                        *(uint32_t*)(outb + (bh * TT + t) * DD + d) = u;
                    }
                }
            } else {
                const float2 b2 = *(const float2*)(bias + n);
                #pragma unroll
                for (int half = 0; half < 2; half++) {
                    const int mm = m + half * 8;
                    float2 o2 = make_float2(acc[mt][nt][half * 2] + b2.x,
                                            acc[mt][nt][half * 2 + 1] + b2.y);
                    *(float2*)(out + (size_t)mm * CC + n) = o2;
                }
            }
        }
    }
}

// ---------------------------------------------------------------------------
// fp16 tensor-core causal flash attention, ldmatrix fragment loads.
// Block 256 / 8 warps; q-tile 128; k-tile 64; K + V^T double-buffered cp.async.
// ---------------------------------------------------------------------------
#define AQSS 72                                  // halves
#define ATTN_SMEM ((128 + 2*64 + 2*64) * AQSS * 2)   // 55296 B

__global__ __launch_bounds__(256) void attn_mma()
{
    extern __shared__ __align__(16) char smc[];
    __half* PQ = (__half*)smc;                      // [128][72] (Q staging + P)
    __half* Ks = PQ + 128 * AQSS;                   // [2][64][72]
    __half* Vt = Ks + 2 * 64 * AQSS;                // [2][64][72]  rows = d
    uint32_t* PQw = (uint32_t*)PQ;
    const uint32_t pq_b = smem_u32(PQ);
    const uint32_t ks_b = smem_u32(Ks);
    const uint32_t vt_b = smem_u32(Vt);

    const int qt = (gridDim.x - 1) - blockIdx.x;    // heavy tiles first
    const int h = blockIdx.y, b = blockIdx.z;
    const int tid = threadIdx.x, lane = tid & 31, w = tid >> 5;
    const int lr = lane >> 2, la = lane & 3;
    const int arow = (lane & 7) + ((lane & 8)  ? 8 : 0);
    const int acol = (lane & 16) ? 8 : 0;
    const int brow = (lane & 7) + ((lane & 16) ? 8 : 0);
    const int bcol = (lane & 8) ? 8 : 0;
    const int q0 = qt * 128;
    const size_t bh = (size_t)(b * HH + h);
    const __half* qg = g_qh + (bh * TT + q0) * DD;
    const __half* kg = g_kh + bh * TT * DD;
    const __half* vg = g_vh + bh * DD * TT;         // [d][t]

    auto load_tile = [&](int kt, int buf) {
        const __half* ksrc = kg + (size_t)kt * 64 * DD;
        #pragma unroll
        for (int i = 0; i < 2; i++) {               // K: 64 rows x 8 segs
            int idx = tid + i * 256;
            int row = idx >> 3, seg = idx & 7;
            cpa16(ks_b + (uint32_t)((buf * 64 + row) * AQSS + seg * 8) * 2,
                  ksrc + (size_t)row * DD + seg * 8);
        }
        #pragma unroll
        for (int i = 0; i < 2; i++) {               // V^T (rows = d)
            int idx = tid + i * 256;
            int row = idx >> 3, seg = idx & 7;
            cpa16(vt_b + (uint32_t)((buf * 64 + row) * AQSS + seg * 8) * 2,
                  vg + (size_t)row * TT + kt * 64 + seg * 8);
        }
        cpa_commit();
    };

    load_tile(0, 0);

    // stage Q (coalesced)
    #pragma unroll
    for (int i = 0; i < 4; i++) {
        int idx = tid + i * 256;
        int row = idx >> 3, seg = idx & 7;
        *(uint4*)&PQ[row * AQSS + seg * 8] =
            *(const uint4*)&qg[(size_t)row * DD + seg * 8];
    }
    __syncthreads();

    // Q fragments via ldmatrix, scaled by C^-0.5 = 2^-5 (exact in fp16)
    uint32_t qa[4][4];
    {
        const __half2 sc = __float2half2_rn(0.03125f);
        #pragma unroll
        for (int ks = 0; ks < 4; ks++) {
            ldsm4(qa[ks], pq_b + (uint32_t)((w * 16 + arow) * AQSS
                                            + ks * 16 + acol) * 2);
            #pragma unroll
            for (int j = 0; j < 4; j++) {
                __half2 v = __hmul2(*(__half2*)&qa[ks][j], sc);
                qa[ks][j] = *(uint32_t*)&v;
            }
        }
    }

    float m0 = -1e30f, m1 = -1e30f, l0 = 0.f, l1 = 0.f;
    float oacc[8][4] = {};

    const int nk = 2 * qt + 2;
    const int row0 = q0 + w * 16 + lr;
    const int row1 = row0 + 8;

    for (int kt = 0; kt < nk; kt++) {
        cpa_wait0();
        __syncthreads();
        if (kt + 1 < nk) load_tile(kt + 1, (kt + 1) & 1);

        const uint32_t kb = ks_b + (uint32_t)(kt & 1) * 64 * AQSS * 2;
        const uint32_t vb = vt_b + (uint32_t)(kt & 1) * 64 * AQSS * 2;

        // ---- S = Q K^T ----
        float sacc[8][4] = {};
        #pragma unroll
        for (int ks = 0; ks < 4; ks++) {
            #pragma unroll
            for (int nf2 = 0; nf2 < 4; nf2++) {
                uint32_t r[4];
                ldsm4(r, kb + (uint32_t)((nf2 * 16 + brow) * AQSS
                                         + ks * 16 + bcol) * 2);
                uint32_t b0[2] = {r[0], r[1]}, b1[2] = {r[2], r[3]};
                mma_f16(sacc[2 * nf2],     qa[ks], b0);
                mma_f16(sacc[2 * nf2 + 1], qa[ks], b1);
            }
        }

        // ---- causal mask ----
        const int s_base = kt * 64;
        if (s_base + 63 > q0 + w * 16) {
            #pragma unroll
            for (int nf = 0; nf < 8; nf++) {
                const int s = s_base + nf * 8 + 2 * la;
                if (s > row0)     sacc[nf][0] = -1e30f;
                if (s + 1 > row0) sacc[nf][1] = -1e30f;
                if (s > row1)     sacc[nf][2] = -1e30f;
                if (s + 1 > row1) sacc[nf][3] = -1e30f;
            }
        }

        // ---- online softmax ----
        float mx0 = -1e30f, mx1 = -1e30f;
        #pragma unroll
        for (int nf = 0; nf < 8; nf++) {
            mx0 = fmaxf(mx0, fmaxf(sacc[nf][0], sacc[nf][1]));
            mx1 = fmaxf(mx1, fmaxf(sacc[nf][2], sacc[nf][3]));
        }
        mx0 = fmaxf(mx0, __shfl_xor_sync(0xffffffffu, mx0, 1));
        mx0 = fmaxf(mx0, __shfl_xor_sync(0xffffffffu, mx0, 2));
        mx1 = fmaxf(mx1, __shfl_xor_sync(0xffffffffu, mx1, 1));
        mx1 = fmaxf(mx1, __shfl_xor_sync(0xffffffffu, mx1, 2));
        const float mn0 = fmaxf(m0, mx0), mn1 = fmaxf(m1, mx1);
        const float c0 = __expf(m0 - mn0), c1 = __expf(m1 - mn1);
        float s0 = 0.f, s1 = 0.f;
        #pragma unroll
        for (int nf = 0; nf < 8; nf++) {
            float p0 = __expf(sacc[nf][0] - mn0);
            float p1 = __expf(sacc[nf][1] - mn0);
            float p2 = __expf(sacc[nf][2] - mn1);
            float p3 = __expf(sacc[nf][3] - mn1);
            s0 += p0 + p1; s1 += p2 + p3;
            PQw[(w * 16 + lr)     * 36 + nf * 4 + la] = pack_h2(p0, p1);
            PQw[(w * 16 + lr + 8) * 36 + nf * 4 + la] = pack_h2(p2, p3);
        }
        s0 += __shfl_xor_sync(0xffffffffu, s0, 1);
        s0 += __shfl_xor_sync(0xffffffffu, s0, 2);
        s1 += __shfl_xor_sync(0xffffffffu, s1, 1);
        s1 += __shfl_xor_sync(0xffffffffu, s1, 2);
        l0 = l0 * c0 + s0;  l1 = l1 * c1 + s1;
        m0 = mn0;           m1 = mn1;
        #pragma unroll
        for (int nf = 0; nf < 8; nf++) {
            oacc[nf][0] *= c0; oacc[nf][1] *= c0;
            oacc[nf][2] *= c1; oacc[nf][3] *= c1;
        }
        __syncwarp();    // P stores visible to ldmatrix within warp

        // ---- O += P V ----
        #pragma unroll
        for (int ks = 0; ks < 4; ks++) {
            uint32_t pa[4];
            ldsm4(pa, pq_b + (uint32_t)((w * 16 + arow) * AQSS
                                        + ks * 16 + acol) * 2);
            #pragma unroll
            for (int nf2 = 0; nf2 < 4; nf2++) {
                uint32_t r[4];
                ldsm4(r, vb + (uint32_t)((nf2 * 16 + brow) * AQSS
                                         + ks * 16 + bcol) * 2);
                uint32_t b0[2] = {r[0], r[1]}, b1[2] = {r[2], r[3]};
                mma_f16(oacc[2 * nf2],     pa, b0);
                mma_f16(oacc[2 * nf2 + 1], pa, b1);
            }
        }
    }

    // ---- normalize, write concat layout fp16 ----
    const float inv0 = 1.0f / l0, inv1 = 1.0f / l1;
    #pragma unroll
    for (int nf = 0; nf < 8; nf++) {
        const int d = h * 64 + nf * 8 + 2 * la;
        *(uint32_t*)&g_yh[(size_t)(b * TT + row0) * CC + d] =
            pack_h2(oacc[nf][0] * inv0, oacc[nf][1] * inv0);
        *(uint32_t*)&g_yh[(size_t)(b * TT + row1) * CC + d] =
            pack_h2(oacc[nf][2] * inv1, oacc[nf][3] * inv1);
    }
}

// ---------------------------------------------------------------------------
extern "C" void kernel_launch(void* const* d_in, const int* in_sizes, int n_in,
                              void* d_out, int out_size)
{
    (void)in_sizes; (void)n_in; (void)out_size;
    const float* x  = (const float*)d_in[0];
    const float* Wq = (const float*)d_in[1];
    const float* Wk = (const float*)d_in[2];
    const float* Wv = (const float*)d_in[3];
    const float* Wp = (const float*)d_in[4];
    const float* bp = (const float*)d_in[5];
    float* out = (float*)d_out;

    cudaFuncSetAttribute(attn_mma,
                         cudaFuncAttributeMaxDynamicSharedMemorySize, ATTN_SMEM);
    cudaFuncSetAttribute(gemm_kernel<0>,
                         cudaFuncAttributeMaxDynamicSharedMemorySize, GEMM_SMEM);
    cudaFuncSetAttribute(gemm_kernel<1>,
                         cudaFuncAttributeMaxDynamicSharedMemorySize, GEMM_SMEM);

    cvt_kernel<<<(BT * CC / 4 + 255) / 256, 256>>>(x, 0, BT * CC / 4);
    cvt_kernel<<<(CC * CC / 4 + 255) / 256, 256>>>(Wp, 1, CC * CC / 4);
    transpose_w<<<dim3(32, 2, 48), dim3(32, 8)>>>(Wq, Wk, Wv);

    gemm_kernel<0><<<dim3(BT / 256, CC / 128, 3), 256, GEMM_SMEM>>>(nullptr, nullptr);

    attn_mma<<<dim3(TT / 128, HH, BB), 256, ATTN_SMEM>>>();

    gemm_kernel<1><<<dim3(BT / 256, CC / 128, 1), 256, GEMM_SMEM>>>(bp, out);
}